// round 16
// baseline (speedup 1.0000x reference)
#include <cuda_runtime.h>
#include <cuda_bf16.h>
#include <cstdint>

#define BB    8192
#define IN_DIM 1024
#define NE    16
#define NH1   1024
#define NH2   512
#define NT    2
#define NHD1  512
#define NHD2  256

// ---------------- scratch (device globals; no allocation allowed) ----------------
__device__ float g_mean[NT * BB * NE];
__device__ float g_std [NT * BB * NE];
__device__ float g_gate[NT * BB * NE];
__device__ int   g_cnt[NE];
__device__ int   g_rows[NE * BB];

__device__ __nv_bfloat16 g_xh[BB * IN_DIM];
__device__ __nv_bfloat16 g_xl[BB * IN_DIM];
__device__ __nv_bfloat16 g_W1h[NE * NH1 * IN_DIM];   // transposed [E,N,K]
__device__ __nv_bfloat16 g_W1l[NE * NH1 * IN_DIM];
__device__ __nv_bfloat16 g_W2h[NE * NH2 * NH1];
__device__ __nv_bfloat16 g_W2l[NE * NH2 * NH1];
__device__ __nv_bfloat16 g_Wh1h[NT * NHD1 * NH2];
__device__ __nv_bfloat16 g_Wh1l[NT * NHD1 * NH2];
__device__ __nv_bfloat16 g_Wh2h[NT * NHD2 * NHD1];
__device__ __nv_bfloat16 g_Wh2l[NT * NHD2 * NHD1];
__device__ __nv_bfloat16 g_hh[NE * BB * NH1];        // compacted expert hidden hi/lo
__device__ __nv_bfloat16 g_hl[NE * BB * NH1];
__device__ float g_eo[NE * BB * NH2];                // expert output fp32 (dense [e][b])
__device__ __nv_bfloat16 g_goh[NT * BB * NH2];       // gate_out hi/lo
__device__ __nv_bfloat16 g_gol[NT * BB * NH2];
__device__ __nv_bfloat16 g_t1h[NT * BB * NHD1];
__device__ __nv_bfloat16 g_t1l[NT * BB * NHD1];
__device__ float g_t2[NT * BB * NHD2];

// ---------------- helpers ----------------
__device__ __forceinline__ uint32_t smem_u32(const void* p) {
    uint32_t a;
    asm("{ .reg .u64 t; cvta.to.shared.u64 t, %1; cvt.u32.u64 %0, t; }" : "=r"(a) : "l"(p));
    return a;
}
__device__ __forceinline__ void ldsm4(uint32_t* r, uint32_t addr) {
    asm volatile("ldmatrix.sync.aligned.m8n8.x4.shared.b16 {%0,%1,%2,%3}, [%4];"
        : "=r"(r[0]), "=r"(r[1]), "=r"(r[2]), "=r"(r[3]) : "r"(addr));
}
__device__ __forceinline__ void mma16816(float* d, const uint32_t* a, const uint32_t* b) {
    asm volatile(
        "mma.sync.aligned.m16n8k16.row.col.f32.bf16.bf16.f32 "
        "{%0,%1,%2,%3}, {%4,%5,%6,%7}, {%8,%9}, {%0,%1,%2,%3};"
        : "+f"(d[0]), "+f"(d[1]), "+f"(d[2]), "+f"(d[3])
        : "r"(a[0]), "r"(a[1]), "r"(a[2]), "r"(a[3]), "r"(b[0]), "r"(b[1]));
}

// 64B-row shared layout swizzle: XOR row bits 1,2 into 16B-column bits 4,5
#define SWZ(o) ((o) ^ (((o) >> 3) & 0x30u))

// ---------------- fp32 -> bf16 hi/lo split helpers ----------------
__device__ __forceinline__ void split1(float v, __nv_bfloat16& h, __nv_bfloat16& l) {
    h = __float2bfloat16(v);
    l = __float2bfloat16(v - __bfloat162float(h));
}
__device__ __forceinline__ void split_store4(__nv_bfloat16* H, __nv_bfloat16* L,
                                             size_t idx, float4 v) {
    __nv_bfloat16 h0, h1, h2, h3, l0, l1, l2, l3;
    split1(v.x, h0, l0); split1(v.y, h1, l1);
    split1(v.z, h2, l2); split1(v.w, h3, l3);
    *(__nv_bfloat162*)&H[idx]     = __halves2bfloat162(h0, h1);
    *(__nv_bfloat162*)&H[idx + 2] = __halves2bfloat162(h2, h3);
    *(__nv_bfloat162*)&L[idx]     = __halves2bfloat162(l0, l1);
    *(__nv_bfloat162*)&L[idx + 2] = __halves2bfloat162(l2, l3);
}

// ---------------- fused conversion kernel ----------------
#define XB      (BB * IN_DIM / 1024)                    // 8192
#define T_W1    (32 * 32 * NE)                          // 16384
#define T_W2    (16 * 32 * NE)                          // 8192
#define T_WH1   (16 * 16 * NT)                          // 512
#define T_WH2   (8 * 16 * NT)                           // 256
#define CONV_BLOCKS (XB + T_W1 + T_W2 + T_WH1 + T_WH2)

__global__ __launch_bounds__(256) void conv_all(
    const float* __restrict__ x,
    const float* __restrict__ We1, const float* __restrict__ We2,
    const float* __restrict__ Wh1, const float* __restrict__ Wh2)
{
    const int tid = threadIdx.x;
    int b = blockIdx.x;

    if (b < XB) {   // x split
        int i = b * 256 + tid;
        float4 v = ((const float4*)x)[i];
        split_store4(g_xh, g_xl, (size_t)i * 4, v);
        return;
    }
    b -= XB;

    const float* in; __nv_bfloat16 *oh, *ol; int K, N, nt;
    if (b < T_W1)      { in = We1; oh = g_W1h;  ol = g_W1l;  K = IN_DIM; N = NH1;  nt = 32; }
    else if ((b -= T_W1) < T_W2)  { in = We2; oh = g_W2h;  ol = g_W2l;  K = NH1;  N = NH2;  nt = 16; }
    else if ((b -= T_W2) < T_WH1) { in = Wh1; oh = g_Wh1h; ol = g_Wh1l; K = NH2;  N = NHD1; nt = 16; }
    else { b -= T_WH1;   in = Wh2; oh = g_Wh2h; ol = g_Wh2l; K = NHD1; N = NHD2; nt = 8;  }

    const int kt = K / 32;
    const int z  = b / (nt * kt);
    const int rm = b - z * (nt * kt);
    const int k0 = (rm / nt) * 32;
    const int n0 = (rm - (rm / nt) * nt) * 32;
    const int tx = tid & 31, ty = tid >> 5;

    __shared__ float tile[32][33];
    const float* I = in + (size_t)z * K * N;
#pragma unroll
    for (int i = 0; i < 4; i++)
        tile[ty + i * 8][tx] = I[(size_t)(k0 + ty + i * 8) * N + n0 + tx];
    __syncthreads();
    __nv_bfloat16* OH = oh + (size_t)z * N * K;
    __nv_bfloat16* OL = ol + (size_t)z * N * K;
#pragma unroll
    for (int i = 0; i < 4; i++) {
        float v = tile[tx][ty + i * 8];
        __nv_bfloat16 h, l; split1(v, h, l);
        size_t o = (size_t)(n0 + ty + i * 8) * K + k0 + tx;
        OH[o] = h; OL[o] = l;
    }
}

// ---------------- threefry2x32 (JAX-compatible) ----------------
__device__ __forceinline__ uint32_t rotl32(uint32_t v, int d) {
    return (v << d) | (v >> (32 - d));
}
__device__ __forceinline__ void threefry2x32(uint32_t k0, uint32_t k1,
                                             uint32_t c0, uint32_t c1,
                                             uint32_t& r0, uint32_t& r1) {
    uint32_t k2 = k0 ^ k1 ^ 0x1BD11BDAu;
    uint32_t x0 = c0 + k0;
    uint32_t x1 = c1 + k1;
#define TF_R(r) { x0 += x1; x1 = rotl32(x1, r); x1 ^= x0; }
    TF_R(13) TF_R(15) TF_R(26) TF_R(6)
    x0 += k1; x1 += k2 + 1u;
    TF_R(17) TF_R(29) TF_R(16) TF_R(24)
    x0 += k2; x1 += k0 + 2u;
    TF_R(13) TF_R(15) TF_R(26) TF_R(6)
    x0 += k0; x1 += k1 + 3u;
    TF_R(17) TF_R(29) TF_R(16) TF_R(24)
    x0 += k1; x1 += k2 + 4u;
    TF_R(13) TF_R(15) TF_R(26) TF_R(6)
    x0 += k2; x1 += k0 + 5u;
#undef TF_R
    r0 = x0; r1 = x1;
}

// ---------------- routing GEMM: mean/std = x @ {Wg,Wn} ----------------
__global__ __launch_bounds__(256) void routing_kernel(const float* __restrict__ x,
                                                      const float* __restrict__ Wg,
                                                      const float* __restrict__ Wn) {
    __shared__ float xsT[64][68];
    __shared__ float ws [64][68];
    const int tid = threadIdx.x;
    const int b0 = blockIdx.x * 64;
    const int c4 = (tid & 15) * 4;
    const int r4 = (tid >> 4) * 4;
    float acc[4][4];
#pragma unroll
    for (int i = 0; i < 4; i++)
#pragma unroll
        for (int j = 0; j < 4; j++) acc[i][j] = 0.f;

    for (int k0 = 0; k0 < IN_DIM; k0 += 64) {
        __syncthreads();
        {
            int bl = tid >> 2;
            int kbase = (tid & 3) * 16;
#pragma unroll
            for (int jj = 0; jj < 4; jj++) {
                float4 v = *(const float4*)&x[(size_t)(b0 + bl) * IN_DIM + k0 + kbase + jj * 4];
                xsT[kbase + jj * 4 + 0][bl] = v.x;
                xsT[kbase + jj * 4 + 1][bl] = v.y;
                xsT[kbase + jj * 4 + 2][bl] = v.z;
                xsT[kbase + jj * 4 + 3][bl] = v.w;
            }
        }
#pragma unroll
        for (int j = 0; j < 16; j++) {
            int idx = j * 256 + tid;
            int k = idx >> 6;
            int c = idx & 63;
            int t = (c >> 4) & 1;
            int e = c & 15;
            const float* Wb = (c < 32) ? Wg : Wn;
            ws[k][c] = Wb[((size_t)t * IN_DIM + (k0 + k)) * NE + e];
        }
        __syncthreads();
#pragma unroll 16
        for (int kk = 0; kk < 64; kk++) {
            float4 wv = *(const float4*)&ws[kk][c4];
            float4 xv = *(const float4*)&xsT[kk][r4];
            float xa[4] = { xv.x, xv.y, xv.z, xv.w };
            float wa[4] = { wv.x, wv.y, wv.z, wv.w };
#pragma unroll
            for (int i = 0; i < 4; i++)
#pragma unroll
                for (int j = 0; j < 4; j++)
                    acc[i][j] = fmaf(xa[i], wa[j], acc[i][j]);
        }
    }
#pragma unroll
    for (int i = 0; i < 4; i++) {
        int b = b0 + r4 + i;
#pragma unroll
        for (int j = 0; j < 4; j++) {
            int c = c4 + j;
            int t = (c >> 4) & 1;
            int e = c & 15;
            float v = acc[i][j];
            if (c < 32)
                g_mean[((size_t)t * BB + b) * NE + e] = v;
            else
                g_std[((size_t)t * BB + b) * NE + e] = fmaxf(v, 0.f) + log1pf(expf(-fabsf(v)));
        }
    }
}

// ---------------- gating: noise + top-4 + softmax + per-expert row lists --------
__global__ __launch_bounds__(256) void gating_kernel() {
    const int b = (blockIdx.x * blockDim.x + threadIdx.x) >> 5;
    const int lane = threadIdx.x & 31;
    if (b >= BB) return;
    const int t = lane >> 4;
    const int e = lane & 15;
    const int n = ((t * BB) + b) * NE + e;

    const float LO = -0.99999994f;   // nextafter(-1, 0) in f32
    float m = g_mean[n];
    float s = g_std[n];
    uint32_t o0, o1;
    threefry2x32(0u, 42u, 0u, (uint32_t)n, o0, o1);
    uint32_t bits = o0 ^ o1;
    float r01 = __uint_as_float((bits >> 9) | 0x3F800000u) - 1.0f;
    float u = fmaxf(LO, fmaf(r01, 2.0f, LO));
    float noise = 1.41421356f * erfinvf(u);
    float noisy = m + noise * s;

    const int base = t * 16;
    int rank = 0;
#pragma unroll
    for (int j = 0; j < NE; j++) {
        float vj = __shfl_sync(0xffffffffu, noisy, base + j);
        rank += ((vj > noisy) || (vj == noisy && j < e)) ? 1 : 0;
    }
    bool sel = rank < 4;
    float vmax = noisy;
#pragma unroll
    for (int off = 8; off >= 1; off >>= 1)
        vmax = fmaxf(vmax, __shfl_xor_sync(0xffffffffu, vmax, off));
    float ev = sel ? expf(noisy - vmax) : 0.f;
    float sum = ev;
#pragma unroll
    for (int off = 8; off >= 1; off >>= 1)
        sum += __shfl_xor_sync(0xffffffffu, sum, off);
    g_gate[n] = sel ? (ev / sum) : 0.f;

    uint32_t bal = __ballot_sync(0xffffffffu, sel);
    if (lane < NE) {
        uint32_t uni = (bal | (bal >> 16)) & 0xffffu;
        if ((uni >> lane) & 1) {
            int pos = atomicAdd(&g_cnt[lane], 1);
            g_rows[lane * BB + pos] = b;
        }
    }
}

// ---------------- mma.sync bf16x3 GEMM (128x128, 8 warps, occ 2, 3-stage) -------
// Distributed cp.async + wait_group pipeline with ONE __syncthreads per chunk.
// Stage = 4 matrices x 128 rows x 64B (XOR-swizzled), 32768 B/stage.
// Matrix offsets within stage: Ah=0, Al=8192, Bh=16384, Bl=24576.
#define STAGE_B   32768
#define TCG_SMEM  (3 * STAGE_B + 1024)

template <int GATHER>
__device__ __forceinline__ void load_chunk(uint32_t st,
    const __nv_bfloat16* Ah, const __nv_bfloat16* Al,
    const __nv_bfloat16* Bh, const __nv_bfloat16* Bl,
    const int* rowSm, int m0, int n0, int k0, int K, int tid)
{
#pragma unroll
    for (int t = 0; t < 4; t++) {
        const __nv_bfloat16* base = (t == 0) ? Ah : (t == 1) ? Al : (t == 2) ? Bh : Bl;
        uint32_t sm0 = st + t * 8192;
#pragma unroll
        for (int j = 0; j < 2; j++) {
            int idx = tid + j * 256;      // 0..511
            int row = idx >> 2;
            int q = idx & 3;              // 16B quarter of the 64B row
            uint32_t off = (uint32_t)row * 64 + q * 16;
            uint32_t dst = sm0 + SWZ(off);
            long long grow;
            if (t < 2) grow = GATHER ? rowSm[row] : (m0 + row);
            else       grow = n0 + row;
            const void* src = base + (size_t)grow * K + k0 + q * 8;
            asm volatile("cp.async.cg.shared.global [%0], [%1], 16;\n"
                         :: "r"(dst), "l"(src) : "memory");
        }
    }
    asm volatile("cp.async.commit_group;\n" ::: "memory");
}

template <int RELU, int SPLIT_OUT, int GATHER_A, int SCATTER_C>
__global__ __launch_bounds__(256, 2) void tc_gemm(
    const __nv_bfloat16* __restrict__ Ah0, const __nv_bfloat16* __restrict__ Al0,
    const __nv_bfloat16* __restrict__ Bh0, const __nv_bfloat16* __restrict__ Bl0,
    const float* __restrict__ bias0,
    float* __restrict__ Cf0, __nv_bfloat16* __restrict__ Ch0, __nv_bfloat16* __restrict__ Cl0,
    int N, int K,
    long long sA, long long sB, long long sBias, long long sC)
{
    extern __shared__ char smem[];
    const uint32_t smem_base = smem_u32(smem);
    const int tid = threadIdx.x;
    const int lane = tid & 31;
    const int w = tid >> 5;
    const int wm = w >> 2;         // 0..1 -> 64-row slab
    const int wn = w & 3;          // 0..3 -> 32-col slab
    const int r = lane >> 2;       // fragment row/col group

    const int z = blockIdx.z;
    const int n0 = blockIdx.x * 128;
    const int m0 = blockIdx.y * 128;

    int mcnt = 0;
    if (GATHER_A || SCATTER_C) {
        mcnt = g_cnt[z];
        if (m0 >= mcnt) return;    // whole CTA exits together
    }

    const __nv_bfloat16* Ah = Ah0 + (size_t)z * sA;
    const __nv_bfloat16* Al = Al0 + (size_t)z * sA;
    const __nv_bfloat16* Bh = Bh0 + (size_t)z * sB;
    const __nv_bfloat16* Bl = Bl0 + (size_t)z * sB;
    const float* bias = bias0 + (size_t)z * sBias;
    float* biasSm = (float*)(smem + 3 * STAGE_B);
    int* rowSm = (int*)(smem + 3 * STAGE_B + 512);

    if (tid < 128) {
        biasSm[tid] = bias[n0 + tid];
        if (GATHER_A || SCATTER_C) {
            int gi = m0 + tid;
            rowSm[tid] = g_rows[z * BB + ((gi < mcnt) ? gi : (mcnt - 1))];
        }
    }
    if (GATHER_A) __syncthreads();   // rowSm must be valid before prologue loads

    // per-lane fragment addressing (pre-swizzle row/col components)
    const uint32_t aRowCol = (uint32_t)(lane & 15) * 64 + (uint32_t)(lane >> 4) * 16;
    const int bq = lane >> 3;      // 0..3
    const uint32_t bRowCol = (uint32_t)((bq >> 1) * 8 + (lane & 7)) * 64
                           + (uint32_t)(bq & 1) * 16;

    float acc[4][4][4];
#pragma unroll
    for (int mi = 0; mi < 4; mi++)
#pragma unroll
        for (int ni = 0; ni < 4; ni++)
#pragma unroll
            for (int j = 0; j < 4; j++) acc[mi][ni][j] = 0.f;

    const int nch = K / 32;
    // prologue: fill 3 stages
    load_chunk<GATHER_A>(smem_base, Ah, Al, Bh, Bl, rowSm, m0, n0, 0, K, tid);
    load_chunk<GATHER_A>(smem_base + STAGE_B, Ah, Al, Bh, Bl, rowSm, m0, n0, 32, K, tid);
    load_chunk<GATHER_A>(smem_base + 2 * STAGE_B, Ah, Al, Bh, Bl, rowSm, m0, n0, 64, K, tid);

    for (int i = 0; i < nch; i++) {
        const int s = i - (i / 3) * 3;
        const uint32_t SB = smem_base + s * STAGE_B;
        if (i == 0)               asm volatile("cp.async.wait_group 2;\n" ::: "memory");
        else if (i + 1 < nch)     asm volatile("cp.async.wait_group 1;\n" ::: "memory");
        else                      asm volatile("cp.async.wait_group 0;\n" ::: "memory");
        __syncthreads();

        if (i >= 1 && i + 2 < nch) {
            const int s2 = (i + 2) - ((i + 2) / 3) * 3;
            load_chunk<GATHER_A>(smem_base + s2 * STAGE_B, Ah, Al, Bh, Bl,
                                 rowSm, m0, n0, (i + 2) * 32, K, tid);
        }

#pragma unroll
        for (int ks = 0; ks < 2; ks++) {
            const uint32_t kb0 = ks * 32;
            uint32_t bh[4][2], bl[4][2];
#pragma unroll
            for (int g = 0; g < 2; g++) {
                uint32_t boff = (uint32_t)(wn * 32 + g * 16) * 64 + kb0 + bRowCol;
                uint32_t t4[4];
                ldsm4(t4, SB + 16384 + SWZ(boff));
                bh[2 * g][0] = t4[0]; bh[2 * g][1] = t4[1];
                bh[2 * g + 1][0] = t4[2]; bh[2 * g + 1][1] = t4[3];
                ldsm4(t4, SB + 24576 + SWZ(boff));
                bl[2 * g][0] = t4[0]; bl[2 * g][1] = t4[1];
                bl[2 * g + 1][0] = t4[2]; bl[2 * g + 1][1] = t4[3];
            }
#pragma unroll
            for (int mi = 0; mi < 4; mi++) {
                uint32_t aoff = (uint32_t)(wm * 64 + mi * 16) * 64 + kb0 + aRowCol;
                uint32_t ah[4], al[4];
                ldsm4(ah, SB + SWZ(aoff));
                ldsm4(al, SB + 8192 + SWZ(aoff));
#pragma unroll
                for (int ni = 0; ni < 4; ni++) {
                    mma16816(acc[mi][ni], ah, bh[ni]);
                    mma16816(acc[mi][ni], ah, bl[ni]);
                    mma16816(acc[mi][ni], al, bh[ni]);
                }
            }
        }
    }

    // epilogue
#pragma unroll
    for (int mi = 0; mi < 4; mi++) {
        const int rl0 = wm * 64 + mi * 16 + r;     // local slot in tile
        const int rl1 = rl0 + 8;
#pragma unroll
        for (int ni = 0; ni < 4; ni++) {
            const int colLoc = wn * 32 + ni * 8 + (lane & 3) * 2;
            const int col = n0 + colLoc;
            float b0 = biasSm[colLoc], b1 = biasSm[colLoc + 1];
            float v0 = acc[mi][ni][0] + b0;
            float v1 = acc[mi][ni][1] + b1;
            float v2 = acc[mi][ni][2] + b0;
            float v3 = acc[mi][ni][3] + b1;
            if (RELU) {
                v0 = fmaxf(v0, 0.f); v1 = fmaxf(v1, 0.f);
                v2 = fmaxf(v2, 0.f); v3 = fmaxf(v3, 0.f);
            }
            if (SPLIT_OUT) {
                const int row = m0 + rl0;
                __nv_bfloat16* Ch = Ch0 + (size_t)z * sC;
                __nv_bfloat16* Cl = Cl0 + (size_t)z * sC;
                __nv_bfloat16 h0, h1, h2, h3, l0, l1, l2, l3;
                split1(v0, h0, l0); split1(v1, h1, l1);
                split1(v2, h2, l2); split1(v3, h3, l3);
                *(__nv_bfloat162*)&Ch[(size_t)row * N + col]       = __halves2bfloat162(h0, h1);
                *(__nv_bfloat162*)&Cl[(size_t)row * N + col]       = __halves2bfloat162(l0, l1);
                *(__nv_bfloat162*)&Ch[(size_t)(row + 8) * N + col] = __halves2bfloat162(h2, h3);
                *(__nv_bfloat162*)&Cl[(size_t)(row + 8) * N + col] = __halves2bfloat162(l2, l3);
            } else if (SCATTER_C) {
                float* Cf = Cf0 + (size_t)z * sC;
                if (m0 + rl0 < mcnt)
                    *(float2*)&Cf[(size_t)rowSm[rl0] * N + col] = make_float2(v0, v1);
                if (m0 + rl1 < mcnt)
                    *(float2*)&Cf[(size_t)rowSm[rl1] * N + col] = make_float2(v2, v3);
            } else {
                const int row = m0 + rl0;
                float* Cf = Cf0 + (size_t)z * sC;
                *(float2*)&Cf[(size_t)row * N + col]       = make_float2(v0, v1);
                *(float2*)&Cf[(size_t)(row + 8) * N + col] = make_float2(v2, v3);
            }
        }
    }
}

// ---------------- gate-weighted combine over experts (writes hi/lo) ----------------
__global__ __launch_bounds__(128) void combine_kernel() {
    const int b = blockIdx.x;
    const int tid = threadIdx.x;
    __shared__ float w0s[NE], w1s[NE];
    if (tid < NE)            w0s[tid] = g_gate[(size_t)b * NE + tid];
    else if (tid < 2 * NE)   w1s[tid - NE] = g_gate[((size_t)BB + b) * NE + (tid - NE)];
    __syncthreads();
    float4 a0 = make_float4(0.f, 0.f, 0.f, 0.f);
    float4 a1 = make_float4(0.f, 0.f, 0.f, 0.f);
#pragma unroll
    for (int e = 0; e < NE; e++) {
        float we0 = w0s[e], we1 = w1s[e];
        if (we0 == 0.f && we1 == 0.f) continue;
        float4 v = *(const float4*)&g_eo[((size_t)e * BB + b) * NH2 + tid * 4];
        a0.x = fmaf(we0, v.x, a0.x); a0.y = fmaf(we0, v.y, a0.y);
        a0.z = fmaf(we0, v.z, a0.z); a0.w = fmaf(we0, v.w, a0.w);
        a1.x = fmaf(we1, v.x, a1.x); a1.y = fmaf(we1, v.y, a1.y);
        a1.z = fmaf(we1, v.z, a1.z); a1.w = fmaf(we1, v.w, a1.w);
    }
    split_store4(g_goh, g_gol, (size_t)b * NH2 + tid * 4, a0);
    split_store4(g_goh, g_gol, ((size_t)BB + b) * NH2 + tid * 4, a1);
}

// ---------------- final head layer: dot(256) + bias ----------------
__global__ __launch_bounds__(256) void final_kernel(const float* __restrict__ Wh3,
                                                    const float* __restrict__ bh3,
                                                    float* __restrict__ out) {
    const int r = (blockIdx.x * blockDim.x + threadIdx.x) >> 5;
    const int lane = threadIdx.x & 31;
    if (r >= NT * BB) return;
    const int t = r / BB;
    const float* row = g_t2 + (size_t)r * NHD2;
    const float* w = Wh3 + t * NHD2;
    float s = 0.f;
#pragma unroll
    for (int k = 0; k < NHD2 / 32; k++)
        s = fmaf(row[lane + 32 * k], w[lane + 32 * k], s);
#pragma unroll
    for (int off = 16; off >= 1; off >>= 1)
        s += __shfl_down_sync(0xffffffffu, s, off);
    if (lane == 0) out[r] = s + bh3[t];
}

// ---------------- launch ----------------
extern "C" void kernel_launch(void* const* d_in, const int* in_sizes, int n_in,
                              void* d_out, int out_size) {
    const float* x   = (const float*)d_in[0];
    const float* We1 = (const float*)d_in[1];
    const float* be1 = (const float*)d_in[2];
    const float* We2 = (const float*)d_in[3];
    const float* be2 = (const float*)d_in[4];
    const float* Wg  = (const float*)d_in[5];
    const float* Wn  = (const float*)d_in[6];
    const float* Wh1 = (const float*)d_in[7];
    const float* bh1 = (const float*)d_in[8];
    const float* Wh2 = (const float*)d_in[9];
    const float* bh2 = (const float*)d_in[10];
    const float* Wh3 = (const float*)d_in[11];
    const float* bh3 = (const float*)d_in[12];
    float* out = (float*)d_out;

    __nv_bfloat16 *pXh, *pXl, *pW1h, *pW1l, *pW2h, *pW2l, *pWh1h, *pWh1l, *pWh2h, *pWh2l;
    __nv_bfloat16 *pHh, *pHl, *pGoh, *pGol, *pT1h, *pT1l;
    float *pEO, *pT2;
    int *pCnt;
    cudaGetSymbolAddress((void**)&pXh, g_xh);   cudaGetSymbolAddress((void**)&pXl, g_xl);
    cudaGetSymbolAddress((void**)&pW1h, g_W1h); cudaGetSymbolAddress((void**)&pW1l, g_W1l);
    cudaGetSymbolAddress((void**)&pW2h, g_W2h); cudaGetSymbolAddress((void**)&pW2l, g_W2l);
    cudaGetSymbolAddress((void**)&pWh1h, g_Wh1h); cudaGetSymbolAddress((void**)&pWh1l, g_Wh1l);
    cudaGetSymbolAddress((void**)&pWh2h, g_Wh2h); cudaGetSymbolAddress((void**)&pWh2l, g_Wh2l);
    cudaGetSymbolAddress((void**)&pHh, g_hh);   cudaGetSymbolAddress((void**)&pHl, g_hl);
    cudaGetSymbolAddress((void**)&pGoh, g_goh); cudaGetSymbolAddress((void**)&pGol, g_gol);
    cudaGetSymbolAddress((void**)&pT1h, g_t1h); cudaGetSymbolAddress((void**)&pT1l, g_t1l);
    cudaGetSymbolAddress((void**)&pEO, g_eo);   cudaGetSymbolAddress((void**)&pT2, g_t2);
    cudaGetSymbolAddress((void**)&pCnt, g_cnt);

    cudaFuncSetAttribute(tc_gemm<1, 1, 1, 0>, cudaFuncAttributeMaxDynamicSharedMemorySize, TCG_SMEM);
    cudaFuncSetAttribute(tc_gemm<0, 0, 0, 1>, cudaFuncAttributeMaxDynamicSharedMemorySize, TCG_SMEM);
    cudaFuncSetAttribute(tc_gemm<1, 1, 0, 0>, cudaFuncAttributeMaxDynamicSharedMemorySize, TCG_SMEM);
    cudaFuncSetAttribute(tc_gemm<1, 0, 0, 0>, cudaFuncAttributeMaxDynamicSharedMemorySize, TCG_SMEM);

    // one-time host-side stream/event setup (no device allocation)
    static cudaStream_t s1 = nullptr;
    static cudaEvent_t evFork, evConv;
    if (s1 == nullptr) {
        cudaStreamCreateWithFlags(&s1, cudaStreamNonBlocking);
        cudaEventCreateWithFlags(&evFork, cudaEventDisableTiming);
        cudaEventCreateWithFlags(&evConv, cudaEventDisableTiming);
    }

    // independent memset first (off the routing->gating critical path)
    cudaMemsetAsync(pCnt, 0, NE * sizeof(int));

    // fork side stream FROM the capture-origin stream, then run conversion
    // there concurrently with routing+gating
    cudaEventRecord(evFork, 0);
    cudaStreamWaitEvent(s1, evFork, 0);
    conv_all<<<CONV_BLOCKS, 256, 0, s1>>>(x, We1, We2, Wh1, Wh2);
    cudaEventRecord(evConv, s1);

    // routing + gating (+ per-expert row lists) on main stream
    routing_kernel<<<BB / 64, 256>>>(x, Wg, Wn);
    gating_kernel<<<BB / 8, 256>>>();

    // join: GEMM1 needs the converted operands
    cudaStreamWaitEvent(0, evConv, 0);

    // expert layer 1 (sparse, gathered rows): relu(x@We1+be1) -> h compact (hi/lo)
    tc_gemm<1, 1, 1, 0><<<dim3(NH1 / 128, BB / 128, NE), 256, TCG_SMEM>>>(
        pXh, pXl, pW1h, pW1l, be1, nullptr, pHh, pHl,
        NH1, IN_DIM, 0LL, (long long)NH1 * IN_DIM, NH1, (long long)BB * NH1);
    // expert layer 2 (sparse, scattered out): h@We2+be2 -> eo dense [e][b]
    tc_gemm<0, 0, 0, 1><<<dim3(NH2 / 128, BB / 128, NE), 256, TCG_SMEM>>>(
        pHh, pHl, pW2h, pW2l, be2, pEO, nullptr, nullptr,
        NH2, NH1, (long long)BB * NH1, (long long)NH2 * NH1, NH2, (long long)BB * NH2);
    // gate-weighted combine -> go (hi/lo)
    combine_kernel<<<BB, 128>>>();
    // head layer 1: relu(go@Wh1+bh1) -> t1 (hi/lo)
    tc_gemm<1, 1, 0, 0><<<dim3(NHD1 / 128, BB / 128, NT), 256, TCG_SMEM>>>(
        pGoh, pGol, pWh1h, pWh1l, bh1, nullptr, pT1h, pT1l,
        NHD1, NH2, (long long)BB * NH2, (long long)NHD1 * NH2, NHD1, (long long)BB * NHD1);
    // head layer 2: relu(t1@Wh2+bh2) -> t2 (fp32)
    tc_gemm<1, 0, 0, 0><<<dim3(NHD2 / 128, BB / 128, NT), 256, TCG_SMEM>>>(
        pT1h, pT1l, pWh2h, pWh2l, bh2, pT2, nullptr, nullptr,
        NHD2, NHD1, (long long)BB * NHD1, (long long)NHD2 * NHD1, NHD2, (long long)BB * NHD2);
    // final projection
    final_kernel<<<(NT * BB) / 8, 256>>>(Wh3, bh3, out);
}

// round 17
// speedup vs baseline: 1.0557x; 1.0557x over previous
#include <cuda_runtime.h>
#include <cuda_bf16.h>
#include <cstdint>

#define BB    8192
#define IN_DIM 1024
#define NE    16
#define NH1   1024
#define NH2   512
#define NT    2
#define NHD1  512
#define NHD2  256

// ---------------- scratch (device globals; no allocation allowed) ----------------
__device__ float g_mean[NT * BB * NE];
__device__ float g_std [NT * BB * NE];
__device__ float g_gate[NT * BB * NE];
__device__ int   g_cnt[NE];
__device__ int   g_rows[NE * BB];

__device__ __nv_bfloat16 g_xh[BB * IN_DIM];
__device__ __nv_bfloat16 g_xl[BB * IN_DIM];
__device__ __nv_bfloat16 g_W1h[NE * NH1 * IN_DIM];   // transposed [E,N,K]
__device__ __nv_bfloat16 g_W1l[NE * NH1 * IN_DIM];
__device__ __nv_bfloat16 g_W2h[NE * NH2 * NH1];
__device__ __nv_bfloat16 g_W2l[NE * NH2 * NH1];
__device__ __nv_bfloat16 g_Wh1h[NT * NHD1 * NH2];
__device__ __nv_bfloat16 g_Wh1l[NT * NHD1 * NH2];
__device__ __nv_bfloat16 g_Wh2h[NT * NHD2 * NHD1];
__device__ __nv_bfloat16 g_Wh2l[NT * NHD2 * NHD1];
__device__ __nv_bfloat16 g_hh[NE * BB * NH1];        // compacted expert hidden hi/lo
__device__ __nv_bfloat16 g_hl[NE * BB * NH1];
__device__ float g_eo[NE * BB * NH2];                // expert output fp32 (dense [e][b])
__device__ __nv_bfloat16 g_goh[NT * BB * NH2];       // gate_out hi/lo
__device__ __nv_bfloat16 g_gol[NT * BB * NH2];
__device__ __nv_bfloat16 g_t1h[NT * BB * NHD1];
__device__ __nv_bfloat16 g_t1l[NT * BB * NHD1];
__device__ float g_t2[NT * BB * NHD2];

// ---------------- helpers ----------------
__device__ __forceinline__ uint32_t smem_u32(const void* p) {
    uint32_t a;
    asm("{ .reg .u64 t; cvta.to.shared.u64 t, %1; cvt.u32.u64 %0, t; }" : "=r"(a) : "l"(p));
    return a;
}
__device__ __forceinline__ void ldsm4(uint32_t* r, uint32_t addr) {
    asm volatile("ldmatrix.sync.aligned.m8n8.x4.shared.b16 {%0,%1,%2,%3}, [%4];"
        : "=r"(r[0]), "=r"(r[1]), "=r"(r[2]), "=r"(r[3]) : "r"(addr));
}
__device__ __forceinline__ void mma16816(float* d, const uint32_t* a, const uint32_t* b) {
    asm volatile(
        "mma.sync.aligned.m16n8k16.row.col.f32.bf16.bf16.f32 "
        "{%0,%1,%2,%3}, {%4,%5,%6,%7}, {%8,%9}, {%0,%1,%2,%3};"
        : "+f"(d[0]), "+f"(d[1]), "+f"(d[2]), "+f"(d[3])
        : "r"(a[0]), "r"(a[1]), "r"(a[2]), "r"(a[3]), "r"(b[0]), "r"(b[1]));
}

// 64B-row shared layout swizzle: XOR row bits 1,2 into 16B-column bits 4,5
#define SWZ(o) ((o) ^ (((o) >> 3) & 0x30u))

// ---------------- fp32 -> bf16 hi/lo split helpers ----------------
__device__ __forceinline__ void split1(float v, __nv_bfloat16& h, __nv_bfloat16& l) {
    h = __float2bfloat16(v);
    l = __float2bfloat16(v - __bfloat162float(h));
}
__device__ __forceinline__ void split_store4(__nv_bfloat16* H, __nv_bfloat16* L,
                                             size_t idx, float4 v) {
    __nv_bfloat16 h0, h1, h2, h3, l0, l1, l2, l3;
    split1(v.x, h0, l0); split1(v.y, h1, l1);
    split1(v.z, h2, l2); split1(v.w, h3, l3);
    *(__nv_bfloat162*)&H[idx]     = __halves2bfloat162(h0, h1);
    *(__nv_bfloat162*)&H[idx + 2] = __halves2bfloat162(h2, h3);
    *(__nv_bfloat162*)&L[idx]     = __halves2bfloat162(l0, l1);
    *(__nv_bfloat162*)&L[idx + 2] = __halves2bfloat162(l2, l3);
}

// ---------------- fused conversion kernel ----------------
#define XB      (BB * IN_DIM / 1024)                    // 8192
#define T_W1    (32 * 32 * NE)                          // 16384
#define T_W2    (16 * 32 * NE)                          // 8192
#define T_WH1   (16 * 16 * NT)                          // 512
#define T_WH2   (8 * 16 * NT)                           // 256
#define CONV_BLOCKS (XB + T_W1 + T_W2 + T_WH1 + T_WH2)

__global__ __launch_bounds__(256) void conv_all(
    const float* __restrict__ x,
    const float* __restrict__ We1, const float* __restrict__ We2,
    const float* __restrict__ Wh1, const float* __restrict__ Wh2)
{
    const int tid = threadIdx.x;
    int b = blockIdx.x;

    if (b < XB) {   // x split
        int i = b * 256 + tid;
        float4 v = ((const float4*)x)[i];
        split_store4(g_xh, g_xl, (size_t)i * 4, v);
        return;
    }
    b -= XB;

    const float* in; __nv_bfloat16 *oh, *ol; int K, N, nt;
    if (b < T_W1)      { in = We1; oh = g_W1h;  ol = g_W1l;  K = IN_DIM; N = NH1;  nt = 32; }
    else if ((b -= T_W1) < T_W2)  { in = We2; oh = g_W2h;  ol = g_W2l;  K = NH1;  N = NH2;  nt = 16; }
    else if ((b -= T_W2) < T_WH1) { in = Wh1; oh = g_Wh1h; ol = g_Wh1l; K = NH2;  N = NHD1; nt = 16; }
    else { b -= T_WH1;   in = Wh2; oh = g_Wh2h; ol = g_Wh2l; K = NHD1; N = NHD2; nt = 8;  }

    const int kt = K / 32;
    const int z  = b / (nt * kt);
    const int rm = b - z * (nt * kt);
    const int k0 = (rm / nt) * 32;
    const int n0 = (rm - (rm / nt) * nt) * 32;
    const int tx = tid & 31, ty = tid >> 5;

    __shared__ float tile[32][33];
    const float* I = in + (size_t)z * K * N;
#pragma unroll
    for (int i = 0; i < 4; i++)
        tile[ty + i * 8][tx] = I[(size_t)(k0 + ty + i * 8) * N + n0 + tx];
    __syncthreads();
    __nv_bfloat16* OH = oh + (size_t)z * N * K;
    __nv_bfloat16* OL = ol + (size_t)z * N * K;
#pragma unroll
    for (int i = 0; i < 4; i++) {
        float v = tile[tx][ty + i * 8];
        __nv_bfloat16 h, l; split1(v, h, l);
        size_t o = (size_t)(n0 + ty + i * 8) * K + k0 + tx;
        OH[o] = h; OL[o] = l;
    }
}

// ---------------- threefry2x32 (JAX-compatible) ----------------
__device__ __forceinline__ uint32_t rotl32(uint32_t v, int d) {
    return (v << d) | (v >> (32 - d));
}
__device__ __forceinline__ void threefry2x32(uint32_t k0, uint32_t k1,
                                             uint32_t c0, uint32_t c1,
                                             uint32_t& r0, uint32_t& r1) {
    uint32_t k2 = k0 ^ k1 ^ 0x1BD11BDAu;
    uint32_t x0 = c0 + k0;
    uint32_t x1 = c1 + k1;
#define TF_R(r) { x0 += x1; x1 = rotl32(x1, r); x1 ^= x0; }
    TF_R(13) TF_R(15) TF_R(26) TF_R(6)
    x0 += k1; x1 += k2 + 1u;
    TF_R(17) TF_R(29) TF_R(16) TF_R(24)
    x0 += k2; x1 += k0 + 2u;
    TF_R(13) TF_R(15) TF_R(26) TF_R(6)
    x0 += k0; x1 += k1 + 3u;
    TF_R(17) TF_R(29) TF_R(16) TF_R(24)
    x0 += k1; x1 += k2 + 4u;
    TF_R(13) TF_R(15) TF_R(26) TF_R(6)
    x0 += k2; x1 += k0 + 5u;
#undef TF_R
    r0 = x0; r1 = x1;
}

// ---------------- routing GEMM: mean/std = x @ {Wg,Wn} ----------------
__global__ __launch_bounds__(256) void routing_kernel(const float* __restrict__ x,
                                                      const float* __restrict__ Wg,
                                                      const float* __restrict__ Wn) {
    __shared__ float xsT[64][68];
    __shared__ float ws [64][68];
    const int tid = threadIdx.x;
    const int b0 = blockIdx.x * 64;
    const int c4 = (tid & 15) * 4;
    const int r4 = (tid >> 4) * 4;
    float acc[4][4];
#pragma unroll
    for (int i = 0; i < 4; i++)
#pragma unroll
        for (int j = 0; j < 4; j++) acc[i][j] = 0.f;

    for (int k0 = 0; k0 < IN_DIM; k0 += 64) {
        __syncthreads();
        {
            int bl = tid >> 2;
            int kbase = (tid & 3) * 16;
#pragma unroll
            for (int jj = 0; jj < 4; jj++) {
                float4 v = *(const float4*)&x[(size_t)(b0 + bl) * IN_DIM + k0 + kbase + jj * 4];
                xsT[kbase + jj * 4 + 0][bl] = v.x;
                xsT[kbase + jj * 4 + 1][bl] = v.y;
                xsT[kbase + jj * 4 + 2][bl] = v.z;
                xsT[kbase + jj * 4 + 3][bl] = v.w;
            }
        }
#pragma unroll
        for (int j = 0; j < 16; j++) {
            int idx = j * 256 + tid;
            int k = idx >> 6;
            int c = idx & 63;
            int t = (c >> 4) & 1;
            int e = c & 15;
            const float* Wb = (c < 32) ? Wg : Wn;
            ws[k][c] = Wb[((size_t)t * IN_DIM + (k0 + k)) * NE + e];
        }
        __syncthreads();
#pragma unroll 16
        for (int kk = 0; kk < 64; kk++) {
            float4 wv = *(const float4*)&ws[kk][c4];
            float4 xv = *(const float4*)&xsT[kk][r4];
            float xa[4] = { xv.x, xv.y, xv.z, xv.w };
            float wa[4] = { wv.x, wv.y, wv.z, wv.w };
#pragma unroll
            for (int i = 0; i < 4; i++)
#pragma unroll
                for (int j = 0; j < 4; j++)
                    acc[i][j] = fmaf(xa[i], wa[j], acc[i][j]);
        }
    }
#pragma unroll
    for (int i = 0; i < 4; i++) {
        int b = b0 + r4 + i;
#pragma unroll
        for (int j = 0; j < 4; j++) {
            int c = c4 + j;
            int t = (c >> 4) & 1;
            int e = c & 15;
            float v = acc[i][j];
            if (c < 32)
                g_mean[((size_t)t * BB + b) * NE + e] = v;
            else
                g_std[((size_t)t * BB + b) * NE + e] = fmaxf(v, 0.f) + log1pf(expf(-fabsf(v)));
        }
    }
}

// ---------------- gating: noise + top-4 + softmax + per-expert row lists --------
__global__ __launch_bounds__(256) void gating_kernel() {
    const int b = (blockIdx.x * blockDim.x + threadIdx.x) >> 5;
    const int lane = threadIdx.x & 31;
    if (b >= BB) return;
    const int t = lane >> 4;
    const int e = lane & 15;
    const int n = ((t * BB) + b) * NE + e;

    const float LO = -0.99999994f;   // nextafter(-1, 0) in f32
    float m = g_mean[n];
    float s = g_std[n];
    uint32_t o0, o1;
    threefry2x32(0u, 42u, 0u, (uint32_t)n, o0, o1);
    uint32_t bits = o0 ^ o1;
    float r01 = __uint_as_float((bits >> 9) | 0x3F800000u) - 1.0f;
    float u = fmaxf(LO, fmaf(r01, 2.0f, LO));
    float noise = 1.41421356f * erfinvf(u);
    float noisy = m + noise * s;

    const int base = t * 16;
    int rank = 0;
#pragma unroll
    for (int j = 0; j < NE; j++) {
        float vj = __shfl_sync(0xffffffffu, noisy, base + j);
        rank += ((vj > noisy) || (vj == noisy && j < e)) ? 1 : 0;
    }
    bool sel = rank < 4;
    float vmax = noisy;
#pragma unroll
    for (int off = 8; off >= 1; off >>= 1)
        vmax = fmaxf(vmax, __shfl_xor_sync(0xffffffffu, vmax, off));
    float ev = sel ? expf(noisy - vmax) : 0.f;
    float sum = ev;
#pragma unroll
    for (int off = 8; off >= 1; off >>= 1)
        sum += __shfl_xor_sync(0xffffffffu, sum, off);
    g_gate[n] = sel ? (ev / sum) : 0.f;

    uint32_t bal = __ballot_sync(0xffffffffu, sel);
    if (lane < NE) {
        uint32_t uni = (bal | (bal >> 16)) & 0xffffu;
        if ((uni >> lane) & 1) {
            int pos = atomicAdd(&g_cnt[lane], 1);
            g_rows[lane * BB + pos] = b;
        }
    }
}

// ---------------- mma.sync bf16x3 GEMM (128x128, 8 warps, occ 2, 3-stage) -------
// Distributed cp.async + wait_group pipeline with ONE __syncthreads per chunk.
// K is compile-time (KT) so the chunk loop arithmetic is static.
// Stage = 4 matrices x 128 rows x 64B (XOR-swizzled), 32768 B/stage.
// Matrix offsets within stage: Ah=0, Al=8192, Bh=16384, Bl=24576.
#define STAGE_B   32768
#define TCG_SMEM  (3 * STAGE_B + 1024)

template <int GATHER, int KT>
__device__ __forceinline__ void load_chunk(uint32_t st,
    const __nv_bfloat16* Ah, const __nv_bfloat16* Al,
    const __nv_bfloat16* Bh, const __nv_bfloat16* Bl,
    const int* rowSm, int m0, int n0, int k0, int tid)
{
#pragma unroll
    for (int t = 0; t < 4; t++) {
        const __nv_bfloat16* base = (t == 0) ? Ah : (t == 1) ? Al : (t == 2) ? Bh : Bl;
        uint32_t sm0 = st + t * 8192;
#pragma unroll
        for (int j = 0; j < 2; j++) {
            int idx = tid + j * 256;      // 0..511
            int row = idx >> 2;
            int q = idx & 3;              // 16B quarter of the 64B row
            uint32_t off = (uint32_t)row * 64 + q * 16;
            uint32_t dst = sm0 + SWZ(off);
            long long grow;
            if (t < 2) grow = GATHER ? rowSm[row] : (m0 + row);
            else       grow = n0 + row;
            const void* src = base + (size_t)grow * KT + k0 + q * 8;
            asm volatile("cp.async.cg.shared.global [%0], [%1], 16;\n"
                         :: "r"(dst), "l"(src) : "memory");
        }
    }
    asm volatile("cp.async.commit_group;\n" ::: "memory");
}

template <int RELU, int SPLIT_OUT, int GATHER_A, int SCATTER_C, int KT>
__global__ __launch_bounds__(256, 2) void tc_gemm(
    const __nv_bfloat16* __restrict__ Ah0, const __nv_bfloat16* __restrict__ Al0,
    const __nv_bfloat16* __restrict__ Bh0, const __nv_bfloat16* __restrict__ Bl0,
    const float* __restrict__ bias0,
    float* __restrict__ Cf0, __nv_bfloat16* __restrict__ Ch0, __nv_bfloat16* __restrict__ Cl0,
    int N,
    long long sA, long long sB, long long sBias, long long sC)
{
    extern __shared__ char smem[];
    const uint32_t smem_base = smem_u32(smem);
    const int tid = threadIdx.x;
    const int lane = tid & 31;
    const int w = tid >> 5;
    const int wm = w >> 2;         // 0..1 -> 64-row slab
    const int wn = w & 3;          // 0..3 -> 32-col slab
    const int r = lane >> 2;       // fragment row/col group

    const int z = blockIdx.z;
    const int n0 = blockIdx.x * 128;
    const int m0 = blockIdx.y * 128;

    int mcnt = 0;
    if (GATHER_A || SCATTER_C) {
        mcnt = g_cnt[z];
        if (m0 >= mcnt) return;    // whole CTA exits together
    }

    const __nv_bfloat16* Ah = Ah0 + (size_t)z * sA;
    const __nv_bfloat16* Al = Al0 + (size_t)z * sA;
    const __nv_bfloat16* Bh = Bh0 + (size_t)z * sB;
    const __nv_bfloat16* Bl = Bl0 + (size_t)z * sB;
    const float* bias = bias0 + (size_t)z * sBias;
    float* biasSm = (float*)(smem + 3 * STAGE_B);
    int* rowSm = (int*)(smem + 3 * STAGE_B + 512);

    if (tid < 128) {
        biasSm[tid] = bias[n0 + tid];
        if (GATHER_A || SCATTER_C) {
            int gi = m0 + tid;
            rowSm[tid] = g_rows[z * BB + ((gi < mcnt) ? gi : (mcnt - 1))];
        }
    }
    if (GATHER_A) __syncthreads();   // rowSm must be valid before prologue loads

    // per-lane fragment addressing (pre-swizzle row/col components)
    const uint32_t aRowCol = (uint32_t)(lane & 15) * 64 + (uint32_t)(lane >> 4) * 16;
    const int bq = lane >> 3;      // 0..3
    const uint32_t bRowCol = (uint32_t)((bq >> 1) * 8 + (lane & 7)) * 64
                           + (uint32_t)(bq & 1) * 16;

    float acc[4][4][4];
#pragma unroll
    for (int mi = 0; mi < 4; mi++)
#pragma unroll
        for (int ni = 0; ni < 4; ni++)
#pragma unroll
            for (int j = 0; j < 4; j++) acc[mi][ni][j] = 0.f;

    constexpr int nch = KT / 32;
    // prologue: fill 3 stages
    load_chunk<GATHER_A, KT>(smem_base, Ah, Al, Bh, Bl, rowSm, m0, n0, 0, tid);
    load_chunk<GATHER_A, KT>(smem_base + STAGE_B, Ah, Al, Bh, Bl, rowSm, m0, n0, 32, tid);
    load_chunk<GATHER_A, KT>(smem_base + 2 * STAGE_B, Ah, Al, Bh, Bl, rowSm, m0, n0, 64, tid);

#pragma unroll 2
    for (int i = 0; i < nch; i++) {
        const int s = i % 3;
        const uint32_t SB = smem_base + s * STAGE_B;
        if (i == 0)               asm volatile("cp.async.wait_group 2;\n" ::: "memory");
        else if (i + 1 < nch)     asm volatile("cp.async.wait_group 1;\n" ::: "memory");
        else                      asm volatile("cp.async.wait_group 0;\n" ::: "memory");
        __syncthreads();

        if (i >= 1 && i + 2 < nch) {
            const int s2 = (i + 2) % 3;
            load_chunk<GATHER_A, KT>(smem_base + s2 * STAGE_B, Ah, Al, Bh, Bl,
                                     rowSm, m0, n0, (i + 2) * 32, tid);
        }

#pragma unroll
        for (int ks = 0; ks < 2; ks++) {
            const uint32_t kb0 = ks * 32;
            uint32_t bh[4][2], bl[4][2];
#pragma unroll
            for (int g = 0; g < 2; g++) {
                uint32_t boff = (uint32_t)(wn * 32 + g * 16) * 64 + kb0 + bRowCol;
                uint32_t t4[4];
                ldsm4(t4, SB + 16384 + SWZ(boff));
                bh[2 * g][0] = t4[0]; bh[2 * g][1] = t4[1];
                bh[2 * g + 1][0] = t4[2]; bh[2 * g + 1][1] = t4[3];
                ldsm4(t4, SB + 24576 + SWZ(boff));
                bl[2 * g][0] = t4[0]; bl[2 * g][1] = t4[1];
                bl[2 * g + 1][0] = t4[2]; bl[2 * g + 1][1] = t4[3];
            }
#pragma unroll
            for (int mi = 0; mi < 4; mi++) {
                uint32_t aoff = (uint32_t)(wm * 64 + mi * 16) * 64 + kb0 + aRowCol;
                uint32_t ah[4], al[4];
                ldsm4(ah, SB + SWZ(aoff));
                ldsm4(al, SB + 8192 + SWZ(aoff));
#pragma unroll
                for (int ni = 0; ni < 4; ni++) {
                    mma16816(acc[mi][ni], ah, bh[ni]);
                    mma16816(acc[mi][ni], ah, bl[ni]);
                    mma16816(acc[mi][ni], al, bh[ni]);
                }
            }
        }
    }

    // epilogue
#pragma unroll
    for (int mi = 0; mi < 4; mi++) {
        const int rl0 = wm * 64 + mi * 16 + r;     // local slot in tile
        const int rl1 = rl0 + 8;
#pragma unroll
        for (int ni = 0; ni < 4; ni++) {
            const int colLoc = wn * 32 + ni * 8 + (lane & 3) * 2;
            const int col = n0 + colLoc;
            float b0 = biasSm[colLoc], b1 = biasSm[colLoc + 1];
            float v0 = acc[mi][ni][0] + b0;
            float v1 = acc[mi][ni][1] + b1;
            float v2 = acc[mi][ni][2] + b0;
            float v3 = acc[mi][ni][3] + b1;
            if (RELU) {
                v0 = fmaxf(v0, 0.f); v1 = fmaxf(v1, 0.f);
                v2 = fmaxf(v2, 0.f); v3 = fmaxf(v3, 0.f);
            }
            if (SPLIT_OUT) {
                const int row = m0 + rl0;
                __nv_bfloat16* Ch = Ch0 + (size_t)z * sC;
                __nv_bfloat16* Cl = Cl0 + (size_t)z * sC;
                __nv_bfloat16 h0, h1, h2, h3, l0, l1, l2, l3;
                split1(v0, h0, l0); split1(v1, h1, l1);
                split1(v2, h2, l2); split1(v3, h3, l3);
                *(__nv_bfloat162*)&Ch[(size_t)row * N + col]       = __halves2bfloat162(h0, h1);
                *(__nv_bfloat162*)&Cl[(size_t)row * N + col]       = __halves2bfloat162(l0, l1);
                *(__nv_bfloat162*)&Ch[(size_t)(row + 8) * N + col] = __halves2bfloat162(h2, h3);
                *(__nv_bfloat162*)&Cl[(size_t)(row + 8) * N + col] = __halves2bfloat162(l2, l3);
            } else if (SCATTER_C) {
                float* Cf = Cf0 + (size_t)z * sC;
                if (m0 + rl0 < mcnt)
                    *(float2*)&Cf[(size_t)rowSm[rl0] * N + col] = make_float2(v0, v1);
                if (m0 + rl1 < mcnt)
                    *(float2*)&Cf[(size_t)rowSm[rl1] * N + col] = make_float2(v2, v3);
            } else {
                const int row = m0 + rl0;
                float* Cf = Cf0 + (size_t)z * sC;
                *(float2*)&Cf[(size_t)row * N + col]       = make_float2(v0, v1);
                *(float2*)&Cf[(size_t)(row + 8) * N + col] = make_float2(v2, v3);
            }
        }
    }
}

// ---------------- gate-weighted combine over experts (writes hi/lo) ----------------
__global__ __launch_bounds__(128) void combine_kernel() {
    const int b = blockIdx.x;
    const int tid = threadIdx.x;
    __shared__ float w0s[NE], w1s[NE];
    if (tid < NE)            w0s[tid] = g_gate[(size_t)b * NE + tid];
    else if (tid < 2 * NE)   w1s[tid - NE] = g_gate[((size_t)BB + b) * NE + (tid - NE)];
    __syncthreads();
    float4 a0 = make_float4(0.f, 0.f, 0.f, 0.f);
    float4 a1 = make_float4(0.f, 0.f, 0.f, 0.f);
#pragma unroll
    for (int e = 0; e < NE; e++) {
        float we0 = w0s[e], we1 = w1s[e];
        if (we0 == 0.f && we1 == 0.f) continue;
        float4 v = *(const float4*)&g_eo[((size_t)e * BB + b) * NH2 + tid * 4];
        a0.x = fmaf(we0, v.x, a0.x); a0.y = fmaf(we0, v.y, a0.y);
        a0.z = fmaf(we0, v.z, a0.z); a0.w = fmaf(we0, v.w, a0.w);
        a1.x = fmaf(we1, v.x, a1.x); a1.y = fmaf(we1, v.y, a1.y);
        a1.z = fmaf(we1, v.z, a1.z); a1.w = fmaf(we1, v.w, a1.w);
    }
    split_store4(g_goh, g_gol, (size_t)b * NH2 + tid * 4, a0);
    split_store4(g_goh, g_gol, ((size_t)BB + b) * NH2 + tid * 4, a1);
}

// ---------------- final head layer: dot(256) + bias ----------------
__global__ __launch_bounds__(256) void final_kernel(const float* __restrict__ Wh3,
                                                    const float* __restrict__ bh3,
                                                    float* __restrict__ out) {
    const int r = (blockIdx.x * blockDim.x + threadIdx.x) >> 5;
    const int lane = threadIdx.x & 31;
    if (r >= NT * BB) return;
    const int t = r / BB;
    const float* row = g_t2 + (size_t)r * NHD2;
    const float* w = Wh3 + t * NHD2;
    float s = 0.f;
#pragma unroll
    for (int k = 0; k < NHD2 / 32; k++)
        s = fmaf(row[lane + 32 * k], w[lane + 32 * k], s);
#pragma unroll
    for (int off = 16; off >= 1; off >>= 1)
        s += __shfl_down_sync(0xffffffffu, s, off);
    if (lane == 0) out[r] = s + bh3[t];
}

// ---------------- launch ----------------
extern "C" void kernel_launch(void* const* d_in, const int* in_sizes, int n_in,
                              void* d_out, int out_size) {
    const float* x   = (const float*)d_in[0];
    const float* We1 = (const float*)d_in[1];
    const float* be1 = (const float*)d_in[2];
    const float* We2 = (const float*)d_in[3];
    const float* be2 = (const float*)d_in[4];
    const float* Wg  = (const float*)d_in[5];
    const float* Wn  = (const float*)d_in[6];
    const float* Wh1 = (const float*)d_in[7];
    const float* bh1 = (const float*)d_in[8];
    const float* Wh2 = (const float*)d_in[9];
    const float* bh2 = (const float*)d_in[10];
    const float* Wh3 = (const float*)d_in[11];
    const float* bh3 = (const float*)d_in[12];
    float* out = (float*)d_out;

    __nv_bfloat16 *pXh, *pXl, *pW1h, *pW1l, *pW2h, *pW2l, *pWh1h, *pWh1l, *pWh2h, *pWh2l;
    __nv_bfloat16 *pHh, *pHl, *pGoh, *pGol, *pT1h, *pT1l;
    float *pEO, *pT2;
    int *pCnt;
    cudaGetSymbolAddress((void**)&pXh, g_xh);   cudaGetSymbolAddress((void**)&pXl, g_xl);
    cudaGetSymbolAddress((void**)&pW1h, g_W1h); cudaGetSymbolAddress((void**)&pW1l, g_W1l);
    cudaGetSymbolAddress((void**)&pW2h, g_W2h); cudaGetSymbolAddress((void**)&pW2l, g_W2l);
    cudaGetSymbolAddress((void**)&pWh1h, g_Wh1h); cudaGetSymbolAddress((void**)&pWh1l, g_Wh1l);
    cudaGetSymbolAddress((void**)&pWh2h, g_Wh2h); cudaGetSymbolAddress((void**)&pWh2l, g_Wh2l);
    cudaGetSymbolAddress((void**)&pHh, g_hh);   cudaGetSymbolAddress((void**)&pHl, g_hl);
    cudaGetSymbolAddress((void**)&pGoh, g_goh); cudaGetSymbolAddress((void**)&pGol, g_gol);
    cudaGetSymbolAddress((void**)&pT1h, g_t1h); cudaGetSymbolAddress((void**)&pT1l, g_t1l);
    cudaGetSymbolAddress((void**)&pEO, g_eo);   cudaGetSymbolAddress((void**)&pT2, g_t2);
    cudaGetSymbolAddress((void**)&pCnt, g_cnt);

    cudaFuncSetAttribute(tc_gemm<1, 1, 1, 0, 1024>, cudaFuncAttributeMaxDynamicSharedMemorySize, TCG_SMEM);
    cudaFuncSetAttribute(tc_gemm<0, 0, 0, 1, 1024>, cudaFuncAttributeMaxDynamicSharedMemorySize, TCG_SMEM);
    cudaFuncSetAttribute(tc_gemm<1, 1, 0, 0, 512>,  cudaFuncAttributeMaxDynamicSharedMemorySize, TCG_SMEM);
    cudaFuncSetAttribute(tc_gemm<1, 0, 0, 0, 512>,  cudaFuncAttributeMaxDynamicSharedMemorySize, TCG_SMEM);

    // independent memset first (off the routing->gating critical path)
    cudaMemsetAsync(pCnt, 0, NE * sizeof(int));

    // fused operand conversion (single launch)
    conv_all<<<CONV_BLOCKS, 256>>>(x, We1, We2, Wh1, Wh2);

    // routing + gating (+ per-expert row lists)
    routing_kernel<<<BB / 64, 256>>>(x, Wg, Wn);
    gating_kernel<<<BB / 8, 256>>>();

    // expert layer 1 (sparse, gathered rows): relu(x@We1+be1) -> h compact (hi/lo)
    tc_gemm<1, 1, 1, 0, 1024><<<dim3(NH1 / 128, BB / 128, NE), 256, TCG_SMEM>>>(
        pXh, pXl, pW1h, pW1l, be1, nullptr, pHh, pHl,
        NH1, 0LL, (long long)NH1 * IN_DIM, NH1, (long long)BB * NH1);
    // expert layer 2 (sparse, scattered out): h@We2+be2 -> eo dense [e][b]
    tc_gemm<0, 0, 0, 1, 1024><<<dim3(NH2 / 128, BB / 128, NE), 256, TCG_SMEM>>>(
        pHh, pHl, pW2h, pW2l, be2, pEO, nullptr, nullptr,
        NH2, (long long)BB * NH1, (long long)NH2 * NH1, NH2, (long long)BB * NH2);
    // gate-weighted combine -> go (hi/lo)
    combine_kernel<<<BB, 128>>>();
    // head layer 1: relu(go@Wh1+bh1) -> t1 (hi/lo)
    tc_gemm<1, 1, 0, 0, 512><<<dim3(NHD1 / 128, BB / 128, NT), 256, TCG_SMEM>>>(
        pGoh, pGol, pWh1h, pWh1l, bh1, nullptr, pT1h, pT1l,
        NHD1, (long long)BB * NH2, (long long)NHD1 * NH2, NHD1, (long long)BB * NHD1);
    // head layer 2: relu(t1@Wh2+bh2) -> t2 (fp32)
    tc_gemm<1, 0, 0, 0, 512><<<dim3(NHD2 / 128, BB / 128, NT), 256, TCG_SMEM>>>(
        pT1h, pT1l, pWh2h, pWh2l, bh2, pT2, nullptr, nullptr,
        NHD2, (long long)BB * NHD1, (long long)NHD2 * NHD1, NHD2, (long long)BB * NHD2);
    // final projection
    final_kernel<<<(NT * BB) / 8, 256>>>(Wh3, bh3, out);
}